// round 9
// baseline (speedup 1.0000x reference)
#include <cuda_runtime.h>
#include <cstdint>

// ---------------- problem constants ----------------
#define NB 64
#define HP 58
#define PIX (HP * HP)                  // 3364 padded pixels per image
#define ROWS_TOTAL (NB * PIX)          // 215296
#define GUARD 64
#define AROWS (ROWS_TOTAL + 2 * GUARD)
#define NCHUNK 3136                    // 200704 / 64 pixels per chunk

// ---------------- device scratch (no allocation allowed) ----------------
__device__ uint4    g_Abit[AROWS];         // bit-packed sign(x), padded NHWC (bit=1 <=> +1)
__device__ uint32_t g_Wbit2[128 * 4 * 12]; // sign(w) k-major: [o][k][t(9)+pad3]
__device__ float    g_alpha[128];          // -2 * scale_o * gamma_o * rsqrt(var+eps)
__device__ float    g_bias[16 * 128];      // (1152 + corr[type]) * sA + sB
__device__ int      g_ctr;                 // persistent-kernel work counter

// ---------------- K0: weights -> bits + folded scales + boundary bias table ----------------
__global__ void k_wbit(const float* __restrict__ w, const float* __restrict__ gamma,
                       const float* __restrict__ beta, const float* __restrict__ mean,
                       const float* __restrict__ var) {
    int o = blockIdx.x;
    int c = threadIdx.x;      // input channel 0..127
    int lane = c & 31;
    int g = c >> 5;           // channel group of 32 -> word index k
    __shared__ float redf[128];
    __shared__ uint32_t s_w[36];   // [t*4 + k]
    __shared__ int s_col[9];

    const float* wp = w + (o * 128 + c) * 9;
    float wv[9];
    float acc = 0.f;
#pragma unroll
    for (int t = 0; t < 9; t++) { wv[t] = wp[t]; acc += fabsf(wv[t]); }
    redf[c] = acc;

#pragma unroll
    for (int t = 0; t < 9; t++) {
        unsigned m = __ballot_sync(0xFFFFFFFFu, wv[t] > 0.f);
        if (lane == 0) s_w[t * 4 + g] = m;
    }
    __syncthreads();
#pragma unroll
    for (int s = 64; s > 0; s >>= 1) {
        if (c < s) redf[c] += redf[c + s];
        __syncthreads();
    }
    if (c < 36) {
        int t = c % 9;
        int k = c / 9;
        g_Wbit2[(o * 4 + k) * 12 + t] = s_w[t * 4 + k];
    }
    if (c < 9) {
        int t = c;
        uint32_t b0 = s_w[t * 4 + 0], b1 = s_w[t * 4 + 1], b2 = s_w[t * 4 + 2], b3 = s_w[t * 4 + 3];
        s_col[t] = 2 * (__popc(b0) + __popc(b1) + __popc(b2) + __popc(b3)) - 128;
    }
    __syncthreads();
    if (c < 16) {
        float scale = redf[0] * (1.0f / 1152.0f);
        float inv = gamma[o] * rsqrtf(var[o] + 1e-5f);
        float sA = scale * inv;
        float sB = beta[o] - mean[o] * inv;
        if (c == 0) g_alpha[o] = -2.0f * sA;
        int type = c;
        int corr = 0;
#pragma unroll
        for (int t = 0; t < 9; t++) {
            int dy = t / 3 - 1, dx = t % 3 - 1;
            bool inval = ((type & 1) && dy < 0) || ((type & 2) && dy > 0) ||
                         ((type & 4) && dx < 0) || ((type & 8) && dx > 0);
            if (inval) corr += s_col[t];
        }
        g_bias[type * 128 + o] = (float)(1152 + corr) * sA + sB;
    }
}

// ---------------- K1a: zero padded border words + reset work counter ----------------
__global__ void k_border() {
    int n = blockIdx.x;
    int tid = threadIdx.x;   // 256
    if (n == 0 && tid == 0) g_ctr = 0;
    uint32_t* ga = (uint32_t*)g_Abit;
    size_t ibase = (size_t)GUARD * 4 + (size_t)n * PIX * 4;
    for (int i = tid; i < 912; i += 256) {
        size_t idx;
        if (i < 464) {
            int hp = (i < 232) ? 0 : 57;
            int r = (i < 232) ? i : (i - 232);
            idx = ibase + ((size_t)hp * HP) * 4 + r;      // r = wp*4+g
        } else {
            int j = i - 464;
            int wp = (j < 224) ? 0 : 57;
            int r = (j < 224) ? j : (j - 224);
            int hp = 1 + (r >> 2);
            idx = ibase + ((size_t)hp * HP + wp) * 4 + (r & 3);
        }
        ga[idx] = 0u;
    }
}

// ---------------- K1b: interior signs, streaming row-per-lane ----------------
__global__ void __launch_bounds__(128)
k_actbit(const float* __restrict__ x) {
    int h = blockIdx.x;    // 0..55
    int n = blockIdx.y;    // 0..63
    int lane = threadIdx.x & 31;
    int g = threadIdx.x >> 5;   // channel group 0..3
    uint32_t* ga = (uint32_t*)g_Abit;

    const float4* xp = (const float4*)(x + ((size_t)(n * 128 + g * 32 + lane)) * 3136 + (size_t)h * 56);
    size_t rowbase = ((size_t)GUARD + (size_t)n * PIX + (size_t)(h + 1) * HP) * 4;

#pragma unroll
    for (int q = 0; q < 14; q++) {
        float4 v = xp[q];
        unsigned m0 = __ballot_sync(0xFFFFFFFFu, v.x > 0.f);
        unsigned m1 = __ballot_sync(0xFFFFFFFFu, v.y > 0.f);
        unsigned m2 = __ballot_sync(0xFFFFFFFFu, v.z > 0.f);
        unsigned m3 = __ballot_sync(0xFFFFFFFFu, v.w > 0.f);
        if (lane < 4) {
            unsigned mj = (lane == 0) ? m0 : (lane == 1) ? m1 : (lane == 2) ? m2 : m3;
            ga[rowbase + (size_t)(q * 4 + lane + 1) * 4 + g] = mj;
        }
    }
}

// ---------------- CSA: 3 words -> (sum, carry), 2 LOP3 ----------------
__device__ __forceinline__ void csa(uint32_t a, uint32_t b, uint32_t c,
                                    uint32_t& s, uint32_t& cy) {
    s = a ^ b ^ c;
    cy = (a & b) | (a & c) | (b & c);
}

__device__ __forceinline__ void stcs(float* p, float v) {
    asm volatile("st.global.cs.f32 [%0], %1;" :: "l"(p), "f"(v) : "memory");
}

// ---------------- K2: persistent split-K XNOR-popcount conv + BN + residual ----------------
__global__ void __launch_bounds__(128, 8)
k_pop(const float* __restrict__ x, float* __restrict__ out) {
    __shared__ uint32_t sW[128 * 48];   // 24 KB, [o][k][12]
    __shared__ float s_alpha[128];
    __shared__ float s_bias0[128];      // interior (type 0) bias
    __shared__ int s_chunk;

    int tid = threadIdx.x;
    for (int i = tid; i < 128 * 48; i += 128) sW[i] = g_Wbit2[i];
    if (tid < 128) { s_alpha[tid] = g_alpha[tid]; s_bias0[tid] = g_bias[tid]; }

    const int half = tid & 1;               // k-pair: 0 -> k{0,1}, 1 -> k{2,3}
    const uint2* ga2 = (const uint2*)g_Abit;

    for (;;) {
        __syncthreads();
        if (tid == 0) s_chunk = atomicAdd(&g_ctr, 1);
        __syncthreads();
        int chunk = s_chunk;
        if (chunk >= NCHUNK) break;

        int p = chunk * 64 + (tid >> 1);
        int n = p / 3136;
        int rem = p - n * 3136;
        int h = rem / 56;
        int w = rem - h * 56;

        // 9 tap half-words (this thread's two k's)
        int arow = GUARD + n * PIX + (h + 1) * HP + (w + 1);
        uint32_t Aw[9][2];
#pragma unroll
        for (int t = 0; t < 9; t++) {
            int dy = t / 3 - 1, dx = t % 3 - 1;
            uint2 v = ga2[(size_t)(arow + dy * HP + dx) * 2 + half];
            Aw[t][0] = v.x; Aw[t][1] = v.y;
        }
        int type = (h == 0 ? 1 : 0) | (h == 55 ? 2 : 0) | (w == 0 ? 4 : 0) | (w == 55 ? 8 : 0);
        int base = n * 401408 + h * 56 + w;
        const float* xr = x + base;
        float* outp = out + base;

#pragma unroll 4
        for (int o = 0; o < 128; o++) {
            const uint32_t* wo = sW + o * 48 + half * 24;
            int acc1 = 0, acc2 = 0;
#pragma unroll
            for (int kk = 0; kk < 2; kk++) {
                const uint32_t* wk = wo + kk * 12;
                uint4 w03 = *(const uint4*)(wk);
                uint4 w47 = *(const uint4*)(wk + 4);
                uint32_t w8 = wk[8];
                uint32_t x0 = Aw[0][kk] ^ w03.x;
                uint32_t x1 = Aw[1][kk] ^ w03.y;
                uint32_t x2 = Aw[2][kk] ^ w03.z;
                uint32_t x3 = Aw[3][kk] ^ w03.w;
                uint32_t x4 = Aw[4][kk] ^ w47.x;
                uint32_t x5 = Aw[5][kk] ^ w47.y;
                uint32_t x6 = Aw[6][kk] ^ w47.z;
                uint32_t x7 = Aw[7][kk] ^ w47.w;
                uint32_t x8 = Aw[8][kk] ^ w8;
                uint32_t s0, c0, s1, c1, s2, c2, s3, c3;
                csa(x0, x1, x2, s0, c0);
                csa(x3, x4, x5, s1, c1);
                csa(x6, x7, x8, s2, c2);
                csa(s0, s1, s2, s3, c3);
                acc1 += __popc(s3);
                acc2 += __popc(c0) + __popc(c1) + __popc(c2) + __popc(c3);
            }
            int Dh = acc1 + 2 * acc2;
            int D = Dh + __shfl_xor_sync(0xFFFFFFFFu, Dh, 1);
            bool mine = (half == 0) ? (o < 64) : (o >= 64);
            if (mine) {
                float bias = type ? g_bias[type * 128 + o] : s_bias0[o];
                float v = fmaf((float)D, s_alpha[o], bias) + xr[o * 3136];
                stcs(outp + o * 3136, v);
            }
        }
    }
}

// ---------------- launch ----------------
extern "C" void kernel_launch(void* const* d_in, const int* in_sizes, int n_in,
                              void* d_out, int out_size) {
    (void)in_sizes; (void)n_in; (void)out_size;
    const float* x     = (const float*)d_in[0];
    const float* w     = (const float*)d_in[1];
    const float* gamma = (const float*)d_in[2];
    const float* beta  = (const float*)d_in[3];
    const float* mean  = (const float*)d_in[4];
    const float* var   = (const float*)d_in[5];
    float* out = (float*)d_out;

    k_wbit<<<128, 128>>>(w, gamma, beta, mean, var);
    k_border<<<NB, 256>>>();
    k_actbit<<<dim3(56, NB), 128>>>(x);

    int dev = 0;
    cudaGetDevice(&dev);
    int smc = 0;
    if (cudaDeviceGetAttribute(&smc, cudaDevAttrMultiProcessorCount, dev) != cudaSuccess || smc <= 0)
        smc = 148;
    k_pop<<<smc * 8, 128>>>(x, out);
}

// round 10
// speedup vs baseline: 1.5077x; 1.5077x over previous
#include <cuda_runtime.h>
#include <cstdint>

// ---------------- problem constants ----------------
#define NB 64
#define HP 58
#define PIX (HP * HP)                  // 3364 padded pixels per image
#define ROWS_TOTAL (NB * PIX)          // 215296
#define GUARD 64
#define AROWS (ROWS_TOTAL + 2 * GUARD)
#define NPXB 6272                      // 200704 / 32 pixels per block
#define NCHUNK (NPXB * 8)              // x8 o-groups of 16

// ---------------- device scratch (no allocation allowed) ----------------
__device__ uint4    g_Abit[AROWS];         // bit-packed sign(x), padded NHWC (bit=1 <=> +1)
__device__ uint32_t g_Wbit2[128 * 4 * 12]; // sign(w) k-major: [o][k][t(9)+pad3]
__device__ float    g_alpha[128];          // -2 * scale_o * gamma_o * rsqrt(var+eps)
__device__ float    g_bias[16 * 128];      // (1152 + corr[type]) * sA + sB
__device__ int      g_ctr;                 // persistent work counter

// ---------------- K0: weights -> bits + folded scales + boundary bias table ----------------
__global__ void k_wbit(const float* __restrict__ w, const float* __restrict__ gamma,
                       const float* __restrict__ beta, const float* __restrict__ mean,
                       const float* __restrict__ var) {
    int o = blockIdx.x;
    int c = threadIdx.x;      // input channel 0..127
    int lane = c & 31;
    int g = c >> 5;           // channel group of 32 -> word index k
    __shared__ float redf[128];
    __shared__ uint32_t s_w[36];   // [t*4 + k]
    __shared__ int s_col[9];

    const float* wp = w + (o * 128 + c) * 9;
    float wv[9];
    float acc = 0.f;
#pragma unroll
    for (int t = 0; t < 9; t++) { wv[t] = wp[t]; acc += fabsf(wv[t]); }
    redf[c] = acc;

#pragma unroll
    for (int t = 0; t < 9; t++) {
        unsigned m = __ballot_sync(0xFFFFFFFFu, wv[t] > 0.f);
        if (lane == 0) s_w[t * 4 + g] = m;
    }
    __syncthreads();
#pragma unroll
    for (int s = 64; s > 0; s >>= 1) {
        if (c < s) redf[c] += redf[c + s];
        __syncthreads();
    }
    if (c < 36) {
        int t = c % 9;
        int k = c / 9;
        g_Wbit2[(o * 4 + k) * 12 + t] = s_w[t * 4 + k];
    }
    if (c < 9) {
        int t = c;
        uint32_t b0 = s_w[t * 4 + 0], b1 = s_w[t * 4 + 1], b2 = s_w[t * 4 + 2], b3 = s_w[t * 4 + 3];
        s_col[t] = 2 * (__popc(b0) + __popc(b1) + __popc(b2) + __popc(b3)) - 128;
    }
    __syncthreads();
    if (c < 16) {
        float scale = redf[0] * (1.0f / 1152.0f);
        float inv = gamma[o] * rsqrtf(var[o] + 1e-5f);
        float sA = scale * inv;
        float sB = beta[o] - mean[o] * inv;
        if (c == 0) g_alpha[o] = -2.0f * sA;
        int type = c;
        int corr = 0;
#pragma unroll
        for (int t = 0; t < 9; t++) {
            int dy = t / 3 - 1, dx = t % 3 - 1;
            bool inval = ((type & 1) && dy < 0) || ((type & 2) && dy > 0) ||
                         ((type & 4) && dx < 0) || ((type & 8) && dx > 0);
            if (inval) corr += s_col[t];
        }
        g_bias[type * 128 + o] = (float)(1152 + corr) * sA + sB;
    }
}

// ---------------- K1a: zero padded border words + reset work counter ----------------
__global__ void k_border() {
    int n = blockIdx.x;
    int tid = threadIdx.x;   // 256
    if (n == 0 && tid == 0) g_ctr = 0;
    uint32_t* ga = (uint32_t*)g_Abit;
    size_t ibase = (size_t)GUARD * 4 + (size_t)n * PIX * 4;
    for (int i = tid; i < 912; i += 256) {
        size_t idx;
        if (i < 464) {
            int hp = (i < 232) ? 0 : 57;
            int r = (i < 232) ? i : (i - 232);
            idx = ibase + ((size_t)hp * HP) * 4 + r;      // r = wp*4+g
        } else {
            int j = i - 464;
            int wp = (j < 224) ? 0 : 57;
            int r = (j < 224) ? j : (j - 224);
            int hp = 1 + (r >> 2);
            idx = ibase + ((size_t)hp * HP + wp) * 4 + (r & 3);
        }
        ga[idx] = 0u;
    }
}

// ---------------- K1b: interior signs, streaming row-per-lane ----------------
__global__ void __launch_bounds__(128)
k_actbit(const float* __restrict__ x) {
    int h = blockIdx.x;    // 0..55
    int n = blockIdx.y;    // 0..63
    int lane = threadIdx.x & 31;
    int g = threadIdx.x >> 5;   // channel group 0..3
    uint32_t* ga = (uint32_t*)g_Abit;

    const float4* xp = (const float4*)(x + ((size_t)(n * 128 + g * 32 + lane)) * 3136 + (size_t)h * 56);
    size_t rowbase = ((size_t)GUARD + (size_t)n * PIX + (size_t)(h + 1) * HP) * 4;

#pragma unroll
    for (int q = 0; q < 14; q++) {
        float4 v = xp[q];
        unsigned m0 = __ballot_sync(0xFFFFFFFFu, v.x > 0.f);
        unsigned m1 = __ballot_sync(0xFFFFFFFFu, v.y > 0.f);
        unsigned m2 = __ballot_sync(0xFFFFFFFFu, v.z > 0.f);
        unsigned m3 = __ballot_sync(0xFFFFFFFFu, v.w > 0.f);
        if (lane < 4) {
            unsigned mj = (lane == 0) ? m0 : (lane == 1) ? m1 : (lane == 2) ? m2 : m3;
            ga[rowbase + (size_t)(q * 4 + lane + 1) * 4 + g] = mj;
        }
    }
}

// ---------------- CSA: 3 words -> (sum, carry), 2 LOP3 ----------------
__device__ __forceinline__ void csa(uint32_t a, uint32_t b, uint32_t c,
                                    uint32_t& s, uint32_t& cy) {
    s = a ^ b ^ c;
    cy = (a & b) | (a & c) | (b & c);
}

__device__ __forceinline__ void stcs(float* p, float v) {
    asm volatile("st.global.cs.f32 [%0], %1;" :: "l"(p), "f"(v) : "memory");
}

// ---------------- K2: warp-persistent XNOR-popcount conv + BN + residual ----------------
__global__ void __launch_bounds__(128, 6)
k_pop(const float* __restrict__ x, float* __restrict__ out) {
    __shared__ uint32_t sW[128 * 48];   // 24 KB, [o][k][12]
    __shared__ float s_bias[16 * 128];  // 8 KB
    __shared__ float s_alpha[128];

    int tid = threadIdx.x;
    for (int i = tid; i < 128 * 48; i += 128) sW[i] = g_Wbit2[i];
    for (int i = tid; i < 16 * 128; i += 128) s_bias[i] = g_bias[i];
    if (tid < 128) s_alpha[tid] = g_alpha[tid];
    __syncthreads();

    const int lane = tid & 31;

    for (;;) {
        int chunk;
        if (lane == 0) chunk = atomicAdd(&g_ctr, 1);
        chunk = __shfl_sync(0xFFFFFFFFu, chunk, 0);
        if (chunk >= NCHUNK) break;

        int og8 = chunk & 7;            // which group of 16 out-channels
        int pb = chunk >> 3;            // 32-pixel block
        int p = pb * 32 + lane;
        int n = p / 3136;
        int rem = p - n * 3136;
        int h = rem / 56;
        int w = rem - h * 56;

        // 9 tap words -> 36 u32 in registers (component-major access: Aw[t*4+k])
        int arow = GUARD + n * PIX + (h + 1) * HP + (w + 1);
        uint32_t Aw[36];
#pragma unroll
        for (int t = 0; t < 9; t++) {
            int dy = t / 3 - 1, dx = t % 3 - 1;
            uint4 v = g_Abit[arow + dy * HP + dx];
            Aw[t * 4 + 0] = v.x; Aw[t * 4 + 1] = v.y;
            Aw[t * 4 + 2] = v.z; Aw[t * 4 + 3] = v.w;
        }
        int type = (h == 0 ? 1 : 0) | (h == 55 ? 2 : 0) | (w == 0 ? 4 : 0) | (w == 55 ? 8 : 0);
        const float* s_biasT = s_bias + type * 128;
        int base = n * 401408 + h * 56 + w;
        const float* xr = x + base;
        float* outp = out + base;

#pragma unroll 1
        for (int oq = 0; oq < 4; oq++) {
#pragma unroll
            for (int j = 0; j < 4; j++) {
                int o = og8 * 16 + oq * 4 + j;
                int acc1 = 0, acc2 = 0;
#pragma unroll
                for (int k = 0; k < 4; k++) {
                    const uint32_t* wk = sW + o * 48 + k * 12;
                    uint4 w03 = *(const uint4*)(wk);
                    uint4 w47 = *(const uint4*)(wk + 4);
                    uint32_t w8 = wk[8];
                    uint32_t x0 = Aw[0 * 4 + k] ^ w03.x;
                    uint32_t x1 = Aw[1 * 4 + k] ^ w03.y;
                    uint32_t x2 = Aw[2 * 4 + k] ^ w03.z;
                    uint32_t x3 = Aw[3 * 4 + k] ^ w03.w;
                    uint32_t x4 = Aw[4 * 4 + k] ^ w47.x;
                    uint32_t x5 = Aw[5 * 4 + k] ^ w47.y;
                    uint32_t x6 = Aw[6 * 4 + k] ^ w47.z;
                    uint32_t x7 = Aw[7 * 4 + k] ^ w47.w;
                    uint32_t x8 = Aw[8 * 4 + k] ^ w8;
                    uint32_t s0, c0, s1, c1, s2, c2, s3, c3;
                    csa(x0, x1, x2, s0, c0);
                    csa(x3, x4, x5, s1, c1);
                    csa(x6, x7, x8, s2, c2);
                    csa(s0, s1, s2, s3, c3);
                    acc1 += __popc(s3);
                    acc2 += __popc(c0) + __popc(c1) + __popc(c2) + __popc(c3);
                }
                int D = acc1 + 2 * acc2;
                float xv = xr[o * 3136];
                stcs(outp + o * 3136, fmaf((float)D, s_alpha[o], s_biasT[o]) + xv);
            }
        }
    }
}

// ---------------- launch ----------------
extern "C" void kernel_launch(void* const* d_in, const int* in_sizes, int n_in,
                              void* d_out, int out_size) {
    (void)in_sizes; (void)n_in; (void)out_size;
    const float* x     = (const float*)d_in[0];
    const float* w     = (const float*)d_in[1];
    const float* gamma = (const float*)d_in[2];
    const float* beta  = (const float*)d_in[3];
    const float* mean  = (const float*)d_in[4];
    const float* var   = (const float*)d_in[5];
    float* out = (float*)d_out;

    k_wbit<<<128, 128>>>(w, gamma, beta, mean, var);
    k_border<<<NB, 256>>>();
    k_actbit<<<dim3(56, NB), 128>>>(x);

    int dev = 0;
    cudaGetDevice(&dev);
    int smc = 0;
    if (cudaDeviceGetAttribute(&smc, cudaDevAttrMultiProcessorCount, dev) != cudaSuccess || smc <= 0)
        smc = 148;
    k_pop<<<smc * 6, 128>>>(x, out);
}

// round 11
// speedup vs baseline: 1.5995x; 1.0609x over previous
#include <cuda_runtime.h>
#include <cstdint>

// ---------------- problem constants ----------------
#define NB 64
#define HP 58
#define PIX (HP * HP)                  // 3364 padded pixels per image
#define ROWS_TOTAL (NB * PIX)          // 215296
#define GUARD 64
#define AROWS (ROWS_TOTAL + 2 * GUARD)
#define NPXB 6272                      // 200704 / 32 pixels per block
#define NCHUNK (NPXB * 4)              // x4 o-groups of 32

// ---------------- device scratch (no allocation allowed) ----------------
__device__ uint4    g_Abit[AROWS];         // bit-packed sign(x), padded NHWC (bit=1 <=> +1)
__device__ uint32_t g_Wbit2[128 * 4 * 12]; // sign(w) k-major: [o][k][t(9)+pad3]
__device__ float    g_alpha[128];          // -2 * scale_o * gamma_o * rsqrt(var+eps)
__device__ float    g_bias[16 * 128];      // (1152 + corr[type]) * sA + sB
__device__ int      g_ctr;                 // persistent work counter

// ---------------- K0: weights -> bits + folded scales + bias table + ctr reset ----------------
__global__ void k_wbit(const float* __restrict__ w, const float* __restrict__ gamma,
                       const float* __restrict__ beta, const float* __restrict__ mean,
                       const float* __restrict__ var) {
    int o = blockIdx.x;
    int c = threadIdx.x;      // input channel 0..127
    int lane = c & 31;
    int g = c >> 5;           // channel group of 32 -> word index k
    __shared__ float redf[128];
    __shared__ uint32_t s_w[36];   // [t*4 + k]
    __shared__ int s_col[9];

    if (o == 0 && c == 0) g_ctr = 0;

    const float* wp = w + (o * 128 + c) * 9;
    float wv[9];
    float acc = 0.f;
#pragma unroll
    for (int t = 0; t < 9; t++) { wv[t] = wp[t]; acc += fabsf(wv[t]); }
    redf[c] = acc;

#pragma unroll
    for (int t = 0; t < 9; t++) {
        unsigned m = __ballot_sync(0xFFFFFFFFu, wv[t] > 0.f);
        if (lane == 0) s_w[t * 4 + g] = m;
    }
    __syncthreads();
#pragma unroll
    for (int s = 64; s > 0; s >>= 1) {
        if (c < s) redf[c] += redf[c + s];
        __syncthreads();
    }
    if (c < 36) {
        int t = c % 9;
        int k = c / 9;
        g_Wbit2[(o * 4 + k) * 12 + t] = s_w[t * 4 + k];
    }
    if (c < 9) {
        int t = c;
        uint32_t b0 = s_w[t * 4 + 0], b1 = s_w[t * 4 + 1], b2 = s_w[t * 4 + 2], b3 = s_w[t * 4 + 3];
        s_col[t] = 2 * (__popc(b0) + __popc(b1) + __popc(b2) + __popc(b3)) - 128;
    }
    __syncthreads();
    if (c < 16) {
        float scale = redf[0] * (1.0f / 1152.0f);
        float inv = gamma[o] * rsqrtf(var[o] + 1e-5f);
        float sA = scale * inv;
        float sB = beta[o] - mean[o] * inv;
        if (c == 0) g_alpha[o] = -2.0f * sA;
        int type = c;
        int corr = 0;
#pragma unroll
        for (int t = 0; t < 9; t++) {
            int dy = t / 3 - 1, dx = t % 3 - 1;
            bool inval = ((type & 1) && dy < 0) || ((type & 2) && dy > 0) ||
                         ((type & 4) && dx < 0) || ((type & 8) && dx > 0);
            if (inval) corr += s_col[t];
        }
        g_bias[type * 128 + o] = (float)(1152 + corr) * sA + sB;
    }
}

// ---------------- K1: interior signs (high-MLP) + border zeroing ----------------
__global__ void __launch_bounds__(128)
k_actbit(const float* __restrict__ x) {
    int hp = blockIdx.x;   // padded row 0..57
    int n = blockIdx.y;    // 0..63
    int tid = threadIdx.x;
    int lane = tid & 31;
    int g = tid >> 5;      // channel group 0..3
    uint32_t* ga = (uint32_t*)g_Abit;
    size_t rowbase = ((size_t)GUARD + (size_t)n * PIX + (size_t)hp * HP) * 4;

    if (hp == 0 || hp == HP - 1) {
        for (int i = tid; i < HP * 4; i += 128) ga[rowbase + i] = 0u;
        return;
    }

    const float4* xp = (const float4*)(x + ((size_t)(n * 128 + g * 32 + lane)) * 3136 + (size_t)(hp - 1) * 56);
    // prefetch entire row -> MLP = 14
    float4 v[14];
#pragma unroll
    for (int q = 0; q < 14; q++) v[q] = xp[q];

    // border column zeros for this row / channel group
    if (lane == 4) ga[rowbase + g] = 0u;                    // wp = 0
    if (lane == 5) ga[rowbase + (size_t)57 * 4 + g] = 0u;   // wp = 57

#pragma unroll
    for (int q = 0; q < 14; q++) {
        unsigned m0 = __ballot_sync(0xFFFFFFFFu, v[q].x > 0.f);
        unsigned m1 = __ballot_sync(0xFFFFFFFFu, v[q].y > 0.f);
        unsigned m2 = __ballot_sync(0xFFFFFFFFu, v[q].z > 0.f);
        unsigned m3 = __ballot_sync(0xFFFFFFFFu, v[q].w > 0.f);
        if (lane < 4) {
            unsigned mj = (lane == 0) ? m0 : (lane == 1) ? m1 : (lane == 2) ? m2 : m3;
            ga[rowbase + (size_t)(q * 4 + lane + 1) * 4 + g] = mj;
        }
    }
}

// ---------------- CSA: 3 words -> (sum, carry), 2 LOP3 ----------------
__device__ __forceinline__ void csa(uint32_t a, uint32_t b, uint32_t c,
                                    uint32_t& s, uint32_t& cy) {
    s = a ^ b ^ c;
    cy = (a & b) | (a & c) | (b & c);
}

__device__ __forceinline__ void stcs(float* p, float v) {
    asm volatile("st.global.cs.f32 [%0], %1;" :: "l"(p), "f"(v) : "memory");
}

// ---------------- K2: warp-persistent XNOR-popcount conv + BN + residual ----------------
__global__ void __launch_bounds__(128, 6)
k_pop(const float* __restrict__ x, float* __restrict__ out) {
    __shared__ uint32_t sW[128 * 48];   // 24 KB, [o][k][12]
    __shared__ float s_bias[16 * 128];  // 8 KB
    __shared__ float s_alpha[128];

    int tid = threadIdx.x;
    for (int i = tid; i < 128 * 48; i += 128) sW[i] = g_Wbit2[i];
    for (int i = tid; i < 16 * 128; i += 128) s_bias[i] = g_bias[i];
    if (tid < 128) s_alpha[tid] = g_alpha[tid];
    __syncthreads();

    const int lane = tid & 31;

    for (;;) {
        int chunk;
        if (lane == 0) chunk = atomicAdd(&g_ctr, 1);
        chunk = __shfl_sync(0xFFFFFFFFu, chunk, 0);
        if (chunk >= NCHUNK) break;

        int og4 = chunk & 3;            // which group of 32 out-channels
        int pb = chunk >> 2;            // 32-pixel block
        int p = pb * 32 + lane;
        int n = p / 3136;
        int rem = p - n * 3136;
        int h = rem / 56;
        int w = rem - h * 56;

        // 9 tap words -> 36 u32 in registers (component-major access: Aw[t*4+k])
        int arow = GUARD + n * PIX + (h + 1) * HP + (w + 1);
        uint32_t Aw[36];
#pragma unroll
        for (int t = 0; t < 9; t++) {
            int dy = t / 3 - 1, dx = t % 3 - 1;
            uint4 v = g_Abit[arow + dy * HP + dx];
            Aw[t * 4 + 0] = v.x; Aw[t * 4 + 1] = v.y;
            Aw[t * 4 + 2] = v.z; Aw[t * 4 + 3] = v.w;
        }
        int type = (h == 0 ? 1 : 0) | (h == 55 ? 2 : 0) | (w == 0 ? 4 : 0) | (w == 55 ? 8 : 0);
        const float* s_biasT = s_bias + type * 128;
        int base = n * 401408 + h * 56 + w;
        const float* xr = x + base;
        float* outp = out + base;

#pragma unroll 1
        for (int oq = 0; oq < 8; oq++) {
#pragma unroll
            for (int j = 0; j < 4; j++) {
                int o = og4 * 32 + oq * 4 + j;
                int acc1 = 0, acc2 = 0;
#pragma unroll
                for (int k = 0; k < 4; k++) {
                    const uint32_t* wk = sW + o * 48 + k * 12;
                    uint4 w03 = *(const uint4*)(wk);
                    uint4 w47 = *(const uint4*)(wk + 4);
                    uint32_t w8 = wk[8];
                    uint32_t x0 = Aw[0 * 4 + k] ^ w03.x;
                    uint32_t x1 = Aw[1 * 4 + k] ^ w03.y;
                    uint32_t x2 = Aw[2 * 4 + k] ^ w03.z;
                    uint32_t x3 = Aw[3 * 4 + k] ^ w03.w;
                    uint32_t x4 = Aw[4 * 4 + k] ^ w47.x;
                    uint32_t x5 = Aw[5 * 4 + k] ^ w47.y;
                    uint32_t x6 = Aw[6 * 4 + k] ^ w47.z;
                    uint32_t x7 = Aw[7 * 4 + k] ^ w47.w;
                    uint32_t x8 = Aw[8 * 4 + k] ^ w8;
                    uint32_t s0, c0, s1, c1, s2, c2, s3, c3;
                    csa(x0, x1, x2, s0, c0);
                    csa(x3, x4, x5, s1, c1);
                    csa(x6, x7, x8, s2, c2);
                    csa(s0, s1, s2, s3, c3);
                    acc1 += __popc(s3);
                    acc2 += __popc(c0) + __popc(c1) + __popc(c2) + __popc(c3);
                }
                int D = acc1 + 2 * acc2;
                float xv = xr[o * 3136];
                stcs(outp + o * 3136, fmaf((float)D, s_alpha[o], s_biasT[o]) + xv);
            }
        }
    }
}

// ---------------- launch ----------------
extern "C" void kernel_launch(void* const* d_in, const int* in_sizes, int n_in,
                              void* d_out, int out_size) {
    (void)in_sizes; (void)n_in; (void)out_size;
    const float* x     = (const float*)d_in[0];
    const float* w     = (const float*)d_in[1];
    const float* gamma = (const float*)d_in[2];
    const float* beta  = (const float*)d_in[3];
    const float* mean  = (const float*)d_in[4];
    const float* var   = (const float*)d_in[5];
    float* out = (float*)d_out;

    k_wbit<<<128, 128>>>(w, gamma, beta, mean, var);
    k_actbit<<<dim3(HP, NB), 128>>>(x);

    int dev = 0;
    cudaGetDevice(&dev);
    int smc = 0;
    if (cudaDeviceGetAttribute(&smc, cudaDevAttrMultiProcessorCount, dev) != cudaSuccess || smc <= 0)
        smc = 148;
    k_pop<<<smc * 6, 128>>>(x, out);
}